// round 7
// baseline (speedup 1.0000x reference)
#include <cuda_runtime.h>
#include <cstdint>

#define ROWS 65536
#define H 256
#define IN_SHAPE 512
#define NA 32
#define NACT 16
#define G3 768   // 3*H

// ---------------- scratch (allocation-free: __device__ globals) -------------
__device__ float g_x [(size_t)ROWS * H];
__device__ float g_gi[(size_t)ROWS * G3];
__device__ float g_gh[(size_t)ROWS * G3];
__device__ float g_h0[(size_t)ROWS * H];
__device__ float g_h1[(size_t)ROWS * H];
__device__ float g_c [(size_t)ROWS * H];
__device__ float g_nb[(size_t)ROWS * NA];
__device__ float g_invn[(size_t)ROWS];

__device__ __forceinline__ float sigm(float x) { return 1.0f / (1.0f + __expf(-x)); }
__device__ __forceinline__ float tanh_fast(float x) {
    return 2.0f / (1.0f + __expf(-2.0f * x)) - 1.0f;
}
__device__ __forceinline__ uint32_t smem_u32(const void* p) {
    uint32_t a;
    asm("{ .reg .u64 t; cvta.to.shared.u64 t, %1; cvt.u32.u64 %0, t; }"
        : "=r"(a) : "l"(p));
    return a;
}
__device__ __forceinline__ uint32_t f2tf32(float v) {
    uint32_t u;
    asm("cvt.rna.tf32.f32 %0, %1;" : "=r"(u) : "f"(v));
    return u;
}
__device__ __forceinline__ void sts32(uint32_t addr, uint32_t v) {
    asm volatile("st.shared.b32 [%0], %1;" :: "r"(addr), "r"(v));
}
__device__ __forceinline__ void lds128(uint32_t& a, uint32_t& b, uint32_t& c,
                                       uint32_t& d, uint32_t addr) {
    asm volatile("ld.shared.v4.b32 {%0,%1,%2,%3}, [%4];"
                 : "=r"(a), "=r"(b), "=r"(c), "=r"(d) : "r"(addr));
}
__device__ __forceinline__ void lds64(uint32_t& a, uint32_t& b, uint32_t addr) {
    asm volatile("ld.shared.v2.b32 {%0,%1}, [%2];"
                 : "=r"(a), "=r"(b) : "r"(addr));
}

// permuted smem store offsets (bytes within stage; A at 0, B at 16384)
__device__ __forceinline__ uint32_t aoff_fn(int r, int f) {
    return ((uint32_t)(((r >> 4) * 4 + (f >> 1)) * 128 + (r & 7) * 16 +
                       ((r >> 3) & 1) + 2 * (f & 1))) * 4u;
}
__device__ __forceinline__ uint32_t boff_fn(int n, int f) {
    return 16384u + ((uint32_t)(((n >> 3) * 4 + (f >> 1)) * 64 + (n & 7) * 8 +
                                (f & 1))) * 4u;
}

#define MMA_TF32_16x8(d, a0, a1, a2, a3, b0, b1) \
    asm volatile( \
        "mma.sync.aligned.m16n8k8.row.col.f32.tf32.tf32.f32 " \
        "{%0,%1,%2,%3}, {%4,%5,%6,%7}, {%8,%9}, {%0,%1,%2,%3};" \
        : "+f"((d)[0]), "+f"((d)[1]), "+f"((d)[2]), "+f"((d)[3]) \
        : "r"(a0), "r"(a1), "r"(a2), "r"(a3), "r"(b0), "r"(b1))

// ---------------- tf32 mma.sync GEMM, fragment-permuted smem -----------------
// C[m,n] = sum_k A[m,k]*B[n,k] + bias[n]   (A: MxK, B: NxK, row-major fp32)
// BM=128, BN=128, BK=32; 512 threads as 4(M) x 4(N) warps; warp tile 32x32.
// A fragments load with LDS.128, B fragments with LDS.64.
#define STAGE_WORDS 8192                 // 4096 A + 4096 B
#define GEMM_SMEM (2 * STAGE_WORDS * 4)  // 64 KB

template <int RELU>
__global__ __launch_bounds__(512) void gemm_mma(
    const float* __restrict__ A, const float* __restrict__ B,
    const float* __restrict__ bias, float* __restrict__ C,
    int M, int N, int K)
{
    extern __shared__ uint32_t sm[];
    const uint32_t smb = smem_u32(sm);

    const int tid = threadIdx.x;
    const int wid = tid >> 5;
    const int lane = tid & 31;
    const int gr = lane >> 2;
    const int tg = lane & 3;
    const int wr = wid >> 2;         // warp M index 0..3
    const int wc = wid & 3;          // warp N index 0..3

    const int bm = blockIdx.y * 128;
    const int bn = blockIdx.x * 128;

    // global staging: 1024 float4 per operand per chunk, 512 threads -> 2 each
    const int r0 = tid >> 3,         f0 = tid & 7;
    const int r1 = (tid + 512) >> 3, f1 = (tid + 512) & 7;

    const float* Ap0 = A + (long)(bm + r0) * K + f0 * 4;
    const float* Ap1 = A + (long)(bm + r1) * K + f1 * 4;
    const float* Bp0 = B + (long)(bn + r0) * K + f0 * 4;
    const float* Bp1 = B + (long)(bn + r1) * K + f1 * 4;

    const uint32_t oa0 = aoff_fn(r0, f0), oa1 = aoff_fn(r1, f1);
    const uint32_t ob0 = boff_fn(r0, f0), ob1 = boff_fn(r1, f1);

    // fragment load base byte-offsets (kk stride: A 512B, B 256B)
    const uint32_t fa0 = (uint32_t)(((wr * 2 + 0) * 4) * 32 + lane) * 16u;
    const uint32_t fa1 = (uint32_t)(((wr * 2 + 1) * 4) * 32 + lane) * 16u;
    uint32_t fb[4];
#pragma unroll
    for (int j = 0; j < 4; j++)
        fb[j] = 16384u + (uint32_t)(((wc * 4 + j) * 4) * 32 + lane) * 8u;

    float acc[2][4][4];
#pragma unroll
    for (int i = 0; i < 2; i++)
#pragma unroll
        for (int j = 0; j < 4; j++)
#pragma unroll
            for (int e = 0; e < 4; e++) acc[i][j][e] = 0.0f;

    const int KT = K >> 5;

    float4 va0 = *(const float4*)Ap0;
    float4 va1 = *(const float4*)Ap1;
    float4 vb0 = *(const float4*)Bp0;
    float4 vb1 = *(const float4*)Bp1;

    for (int kt = 0; kt < KT; kt++) {
        const uint32_t sb = smb + (uint32_t)(kt & 1) * (STAGE_WORDS * 4);
        // stage current chunk (converted to tf32, permuted)
        sts32(sb + oa0 +  0, f2tf32(va0.x)); sts32(sb + oa0 + 16, f2tf32(va0.y));
        sts32(sb + oa0 + 32, f2tf32(va0.z)); sts32(sb + oa0 + 48, f2tf32(va0.w));
        sts32(sb + oa1 +  0, f2tf32(va1.x)); sts32(sb + oa1 + 16, f2tf32(va1.y));
        sts32(sb + oa1 + 32, f2tf32(va1.z)); sts32(sb + oa1 + 48, f2tf32(va1.w));
        sts32(sb + ob0 +  0, f2tf32(vb0.x)); sts32(sb + ob0 +  8, f2tf32(vb0.y));
        sts32(sb + ob0 + 16, f2tf32(vb0.z)); sts32(sb + ob0 + 24, f2tf32(vb0.w));
        sts32(sb + ob1 +  0, f2tf32(vb1.x)); sts32(sb + ob1 +  8, f2tf32(vb1.y));
        sts32(sb + ob1 + 16, f2tf32(vb1.z)); sts32(sb + ob1 + 24, f2tf32(vb1.w));

        // prefetch next chunk
        if (kt + 1 < KT) {
            const int ko = (kt + 1) << 5;
            va0 = *(const float4*)(Ap0 + ko);
            va1 = *(const float4*)(Ap1 + ko);
            vb0 = *(const float4*)(Bp0 + ko);
            vb1 = *(const float4*)(Bp1 + ko);
        }
        __syncthreads();

#pragma unroll
        for (int kk = 0; kk < 4; kk++) {
            uint32_t af[2][4], bfr[4][2];
            lds128(af[0][0], af[0][1], af[0][2], af[0][3], sb + fa0 + kk * 512);
            lds128(af[1][0], af[1][1], af[1][2], af[1][3], sb + fa1 + kk * 512);
#pragma unroll
            for (int j = 0; j < 4; j++)
                lds64(bfr[j][0], bfr[j][1], sb + fb[j] + kk * 256);
#pragma unroll
            for (int i = 0; i < 2; i++)
#pragma unroll
                for (int j = 0; j < 4; j++)
                    MMA_TF32_16x8(acc[i][j], af[i][0], af[i][1], af[i][2], af[i][3],
                                  bfr[j][0], bfr[j][1]);
        }
    }

    // epilogue
#pragma unroll
    for (int j = 0; j < 4; j++) {
        const int col = bn + wc * 32 + 8 * j + 2 * tg;
        const float2 bb = *(const float2*)&bias[col];
#pragma unroll
        for (int i = 0; i < 2; i++) {
            const long row = (long)(bm + wr * 32 + 16 * i + gr);
            float2 v0, v1;
            v0.x = acc[i][j][0] + bb.x;
            v0.y = acc[i][j][1] + bb.y;
            v1.x = acc[i][j][2] + bb.x;
            v1.y = acc[i][j][3] + bb.y;
            if (RELU) {
                v0.x = fmaxf(v0.x, 0.0f); v0.y = fmaxf(v0.y, 0.0f);
                v1.x = fmaxf(v1.x, 0.0f); v1.y = fmaxf(v1.y, 0.0f);
            }
            *(float2*)&C[row * N + col] = v0;
            *(float2*)&C[(row + 8) * N + col] = v1;
        }
    }
}

// ---------------- GRU gate fusion -------------------------------------------
__global__ __launch_bounds__(256) void gru_gates(
    const float* __restrict__ gi, const float* __restrict__ gh,
    const float* __restrict__ hstate,
    float* __restrict__ out0, float* __restrict__ out1)
{
    int idx = blockIdx.x * 256 + threadIdx.x;
    int row = idx >> 6;
    int c = (idx & 63) << 2;
    long gbase = (long)row * G3 + c;
    long hbase = (long)row * H + c;

    float4 ir = *(const float4*)&gi[gbase];
    float4 iz = *(const float4*)&gi[gbase + 256];
    float4 in_ = *(const float4*)&gi[gbase + 512];
    float4 hr = *(const float4*)&gh[gbase];
    float4 hz = *(const float4*)&gh[gbase + 256];
    float4 hn = *(const float4*)&gh[gbase + 512];
    float4 hv = *(const float4*)&hstate[hbase];

    float4 o;
    { float r = sigm(ir.x + hr.x), z = sigm(iz.x + hz.x);
      float n = tanh_fast(in_.x + r * hn.x); o.x = (1.0f - z) * n + z * hv.x; }
    { float r = sigm(ir.y + hr.y), z = sigm(iz.y + hz.y);
      float n = tanh_fast(in_.y + r * hn.y); o.y = (1.0f - z) * n + z * hv.y; }
    { float r = sigm(ir.z + hr.z), z = sigm(iz.z + hz.z);
      float n = tanh_fast(in_.z + r * hn.z); o.z = (1.0f - z) * n + z * hv.z; }
    { float r = sigm(ir.w + hr.w), z = sigm(iz.w + hz.w);
      float n = tanh_fast(in_.w + r * hn.w); o.w = (1.0f - z) * n + z * hv.w; }
    *(float4*)&out0[hbase] = o;
    if (out1) *(float4*)&out1[hbase] = o;
}

// ---------------- neighbor extraction ----------------------------------------
__global__ __launch_bounds__(256) void nb_kernel(
    const float* __restrict__ inp, float* __restrict__ nb, float* __restrict__ invn)
{
    int idx = blockIdx.x * 256 + threadIdx.x;
    int row = idx >> 5;
    int j = idx & 31;
    int i = row & 31;
    float v = 0.0f;
    if (j != i) {
        int k = (j > i) ? (j - 1) : j;
        v = inp[(long)row * IN_SHAPE + 260 + 8 * k];
    }
    float s = v;
#pragma unroll
    for (int o = 16; o > 0; o >>= 1) s += __shfl_xor_sync(0xffffffffu, s, o);
    nb[idx] = v;
    if (j == 0) invn[row] = 1.0f / s;
}

// ---------------- comm mix ---------------------------------------------------
__global__ __launch_bounds__(256) void comm_mix(
    const float* __restrict__ h, const float* __restrict__ nb,
    const float* __restrict__ invn, float* __restrict__ out)
{
    __shared__ float hs[32][256];
    __shared__ float At[32][36];
    __shared__ float sinv[32];

    int b = blockIdx.x;
    int tid = threadIdx.x;
    const float* hb = h + (long)b * 32 * 256;

#pragma unroll
    for (int t = tid; t < 2048; t += 256) {
        int r = t >> 6;
        int c4 = (t & 63) << 2;
        *(float4*)&hs[r][c4] = *(const float4*)&hb[r * 256 + c4];
    }
#pragma unroll
    for (int t = tid; t < 1024; t += 256) {
        int i = t >> 5;
        int j = t & 31;
        At[j][i] = nb[(long)(b * 32 + i) * 32 + j];
    }
    if (tid < 32) sinv[tid] = invn[b * 32 + tid];
    __syncthreads();

    float acc[32];
#pragma unroll
    for (int i = 0; i < 32; i++) acc[i] = 0.0f;

#pragma unroll 4
    for (int j = 0; j < 32; j++) {
        float hv = hs[j][tid];
#pragma unroll
        for (int i4 = 0; i4 < 32; i4 += 4) {
            float4 a = *(const float4*)&At[j][i4];
            acc[i4 + 0] += a.x * hv;
            acc[i4 + 1] += a.y * hv;
            acc[i4 + 2] += a.z * hv;
            acc[i4 + 3] += a.w * hv;
        }
    }
#pragma unroll
    for (int i = 0; i < 32; i++)
        out[(long)(b * 32 + i) * 256 + tid] = acc[i] * sinv[i];
}

// ---------------- q projection -----------------------------------------------
__global__ __launch_bounds__(256) void qproj(
    const float* __restrict__ h, const float* __restrict__ W2,
    const float* __restrict__ b2, float* __restrict__ q)
{
    __shared__ float ws[16][260];
    __shared__ float hsm[16][256];
    int tid = threadIdx.x;

#pragma unroll
    for (int t = tid; t < 1024; t += 256) {
        int n = t >> 6;
        int k4 = (t & 63) << 2;
        *(float4*)&ws[n][k4] = *(const float4*)&W2[n * 256 + k4];
    }
    const float* hb = h + (long)blockIdx.x * 16 * 256;
#pragma unroll
    for (int t = tid; t < 1024; t += 256) {
        int r = t >> 6;
        int k4 = (t & 63) << 2;
        *(float4*)&hsm[r][k4] = *(const float4*)&hb[r * 256 + k4];
    }
    __syncthreads();

    int r = tid >> 4;
    int n = tid & 15;
    float s = 0.0f;
#pragma unroll 8
    for (int k = 0; k < 256; k += 4) {
        float4 hv = *(const float4*)&hsm[r][k];
        float4 wv = *(const float4*)&ws[n][k];
        s += hv.x * wv.x + hv.y * wv.y + hv.z * wv.z + hv.w * wv.w;
    }
    q[(long)(blockIdx.x * 16 + r) * 16 + n] = s + b2[n];
}

// ---------------- orchestration ----------------------------------------------
extern "C" void kernel_launch(void* const* d_in, const int* in_sizes, int n_in,
                              void* d_out, int out_size)
{
    (void)in_sizes; (void)n_in; (void)out_size;
    const float* inputs = (const float*)d_in[0];
    const float* hidden = (const float*)d_in[1];
    const float* W1     = (const float*)d_in[2];
    const float* b1     = (const float*)d_in[3];
    const float* rWih   = (const float*)d_in[4];
    const float* rWhh   = (const float*)d_in[5];
    const float* rbih   = (const float*)d_in[6];
    const float* rbhh   = (const float*)d_in[7];
    const float* cWih   = (const float*)d_in[8];
    const float* cWhh   = (const float*)d_in[9];
    const float* cbih   = (const float*)d_in[10];
    const float* cbhh   = (const float*)d_in[11];
    const float* W2     = (const float*)d_in[12];
    const float* b2     = (const float*)d_in[13];

    float* q_out = (float*)d_out;
    float* hrnn_out = q_out + (long)ROWS * NACT;

    float *x, *gi, *gh, *h0, *h1, *c, *nb, *invn;
    cudaGetSymbolAddress((void**)&x, g_x);
    cudaGetSymbolAddress((void**)&gi, g_gi);
    cudaGetSymbolAddress((void**)&gh, g_gh);
    cudaGetSymbolAddress((void**)&h0, g_h0);
    cudaGetSymbolAddress((void**)&h1, g_h1);
    cudaGetSymbolAddress((void**)&c, g_c);
    cudaGetSymbolAddress((void**)&nb, g_nb);
    cudaGetSymbolAddress((void**)&invn, g_invn);

    cudaFuncSetAttribute(gemm_mma<0>, cudaFuncAttributeMaxDynamicSharedMemorySize, GEMM_SMEM);
    cudaFuncSetAttribute(gemm_mma<1>, cudaFuncAttributeMaxDynamicSharedMemorySize, GEMM_SMEM);

    dim3 blk(256);
    dim3 gblk(512);

    nb_kernel<<<ROWS * 32 / 256, blk>>>(inputs, nb, invn);

    // x = relu(inputs @ W1^T + b1)
    gemm_mma<1><<<dim3(H / 128, ROWS / 128), gblk, GEMM_SMEM>>>(inputs, W1, b1, x, ROWS, H, IN_SHAPE);

    // h_rnn = GRU(x, hidden)
    gemm_mma<0><<<dim3(G3 / 128, ROWS / 128), gblk, GEMM_SMEM>>>(x, rWih, rbih, gi, ROWS, G3, H);
    gemm_mma<0><<<dim3(G3 / 128, ROWS / 128), gblk, GEMM_SMEM>>>(hidden, rWhh, rbhh, gh, ROWS, G3, H);
    gru_gates<<<ROWS * 64 / 256, blk>>>(gi, gh, hidden, h0, hrnn_out);

    float* hc = h0;
    float* hn = h1;
    for (int s = 0; s < 4; s++) {
        comm_mix<<<ROWS / NA, blk>>>(hc, nb, invn, c);
        gemm_mma<0><<<dim3(G3 / 128, ROWS / 128), gblk, GEMM_SMEM>>>(hc, cWih, cbih, gi, ROWS, G3, H);
        gemm_mma<0><<<dim3(G3 / 128, ROWS / 128), gblk, GEMM_SMEM>>>(c, cWhh, cbhh, gh, ROWS, G3, H);
        gru_gates<<<ROWS * 64 / 256, blk>>>(gi, gh, c, hn, nullptr);
        float* t2 = hc; hc = hn; hn = t2;
    }

    qproj<<<ROWS / 16, blk>>>(hc, W2, b2, q_out);
}

// round 8
// speedup vs baseline: 1.2916x; 1.2916x over previous
#include <cuda_runtime.h>
#include <cstdint>

#define ROWS 65536
#define H 256
#define IN_SHAPE 512
#define NA 32
#define NACT 16
#define G3 768   // 3*H

// ---------------- scratch (allocation-free: __device__ globals) -------------
__device__ float g_x [(size_t)ROWS * H];
__device__ float g_gi[(size_t)ROWS * G3];
__device__ float g_gh[(size_t)ROWS * G3];
__device__ float g_h0[(size_t)ROWS * H];
__device__ float g_h1[(size_t)ROWS * H];
__device__ float g_c [(size_t)ROWS * H];
__device__ float g_nb[(size_t)ROWS * NA];
__device__ float g_invn[(size_t)ROWS];

__device__ __forceinline__ float sigm(float x) { return 1.0f / (1.0f + __expf(-x)); }
__device__ __forceinline__ float tanh_fast(float x) {
    return 2.0f / (1.0f + __expf(-2.0f * x)) - 1.0f;
}
__device__ __forceinline__ uint32_t smem_u32(const void* p) {
    uint32_t a;
    asm("{ .reg .u64 t; cvta.to.shared.u64 t, %1; cvt.u32.u64 %0, t; }"
        : "=r"(a) : "l"(p));
    return a;
}
__device__ __forceinline__ uint32_t f2tf32(float v) {
    uint32_t u;
    asm("cvt.rna.tf32.f32 %0, %1;" : "=r"(u) : "f"(v));
    return u;
}
__device__ __forceinline__ void lds64(uint32_t& a, uint32_t& b, uint32_t addr) {
    asm volatile("ld.shared.v2.b32 {%0,%1}, [%2];"
                 : "=r"(a), "=r"(b) : "r"(addr));
}

#define MMA_TF32_16x8(d, a0, a1, a2, a3, b0, b1) \
    asm volatile( \
        "mma.sync.aligned.m16n8k8.row.col.f32.tf32.tf32.f32 " \
        "{%0,%1,%2,%3}, {%4,%5,%6,%7}, {%8,%9}, {%0,%1,%2,%3};" \
        : "+f"((d)[0]), "+f"((d)[1]), "+f"((d)[2]), "+f"((d)[3]) \
        : "r"(a0), "r"(a1), "r"(a2), "r"(a3), "r"(b0), "r"(b1))

// k-permutation within each 8-wide block: logical k -> storage word
// s(k) = (k & ~7) + 2*(k & 3) + ((k >> 2) & 1)
// so logical pair (kb+tg, kb+tg+4) sits at adjacent words (kb+2tg, kb+2tg+1).
#define RSTRIDE 38   // words per 32-word row (152B, 8B-aligned rows)

// ---------------- tf32 mma.sync GEMM (R3 skeleton + LDS.64 fragments) --------
// C[m,n] = sum_k A[m,k]*B[n,k] + bias[n]   (A: MxK, B: NxK, row-major fp32)
// BM=128, BN=128, BK=32; 8 warps as 2(M) x 4(N); warp tile 64x32.
template <int RELU>
__global__ __launch_bounds__(256) void gemm_mma(
    const float* __restrict__ A, const float* __restrict__ B,
    const float* __restrict__ bias, float* __restrict__ C,
    int M, int N, int K)
{
    __shared__ uint32_t As[128 * RSTRIDE];
    __shared__ uint32_t Bs[128 * RSTRIDE];

    const int tid = threadIdx.x;
    const int wid = tid >> 5;
    const int lane = tid & 31;
    const int gr = lane >> 2;
    const int tg = lane & 3;

    const int bm = blockIdx.y * 128;
    const int bn = blockIdx.x * 128;
    const int wm = (wid & 1) * 64;
    const int wn = (wid >> 1) * 32;

    const int lr = tid >> 3;        // rows lr, lr+32, lr+64, lr+96
    const int lf = tid & 7;         // float4 index within 32-k chunk

    const float* Ap = A + (long)(bm + lr) * K + lf * 4;
    const float* Bp = B + (long)(bn + lr) * K + lf * 4;
    const long strideA = (long)32 * K;

    // permuted store word indices for this thread's float4 (k = lf*4 + d):
    // d=0..3 -> s = 8*(lf>>1) + (lf&1) + 2d
    const int sBase = 8 * (lf >> 1) + (lf & 1);

    const uint32_t aBase = smem_u32(As);
    const uint32_t bBase = smem_u32(Bs);

    float acc[4][4][4];
#pragma unroll
    for (int i = 0; i < 4; i++)
#pragma unroll
        for (int j = 0; j < 4; j++)
#pragma unroll
            for (int e = 0; e < 4; e++) acc[i][j][e] = 0.0f;

    float4 ar[4], br[4];
#pragma unroll
    for (int i = 0; i < 4; i++) {
        ar[i] = *(const float4*)(Ap + i * strideA);
        br[i] = *(const float4*)(Bp + i * strideA);
    }

    for (int k0 = 0; k0 < K; k0 += 32) {
        __syncthreads();
#pragma unroll
        for (int i = 0; i < 4; i++) {
            const int r = lr + i * 32;
            uint32_t* aw = (uint32_t*)As + r * RSTRIDE + sBase;
            uint32_t* bw = (uint32_t*)Bs + r * RSTRIDE + sBase;
            aw[0] = f2tf32(ar[i].x); aw[2] = f2tf32(ar[i].y);
            aw[4] = f2tf32(ar[i].z); aw[6] = f2tf32(ar[i].w);
            bw[0] = f2tf32(br[i].x); bw[2] = f2tf32(br[i].y);
            bw[4] = f2tf32(br[i].z); bw[6] = f2tf32(br[i].w);
        }
        __syncthreads();

        if (k0 + 32 < K) {
#pragma unroll
            for (int i = 0; i < 4; i++) {
                ar[i] = *(const float4*)(Ap + (k0 + 32) + i * strideA);
                br[i] = *(const float4*)(Bp + (k0 + 32) + i * strideA);
            }
        }

#pragma unroll
        for (int kk = 0; kk < 4; kk++) {
            const uint32_t kwb = (uint32_t)(kk * 8 + 2 * tg) * 4u;
            uint32_t af[4][4];
            uint32_t bf[4][2];
#pragma unroll
            for (int i = 0; i < 4; i++) {
                const int r0 = wm + 16 * i + gr;
                lds64(af[i][0], af[i][2], aBase + (uint32_t)(r0 * RSTRIDE) * 4u + kwb);
                lds64(af[i][1], af[i][3], aBase + (uint32_t)((r0 + 8) * RSTRIDE) * 4u + kwb);
            }
#pragma unroll
            for (int j = 0; j < 4; j++) {
                const int n0 = wn + 8 * j + gr;
                lds64(bf[j][0], bf[j][1], bBase + (uint32_t)(n0 * RSTRIDE) * 4u + kwb);
            }
#pragma unroll
            for (int i = 0; i < 4; i++)
#pragma unroll
                for (int j = 0; j < 4; j++)
                    MMA_TF32_16x8(acc[i][j], af[i][0], af[i][1], af[i][2], af[i][3],
                                  bf[j][0], bf[j][1]);
        }
    }

#pragma unroll
    for (int j = 0; j < 4; j++) {
        const int col = bn + wn + 8 * j + 2 * tg;
        const float2 bb = *(const float2*)&bias[col];
#pragma unroll
        for (int i = 0; i < 4; i++) {
            const long r0 = (long)(bm + wm + 16 * i + gr);
            float2 v0, v1;
            v0.x = acc[i][j][0] + bb.x;
            v0.y = acc[i][j][1] + bb.y;
            v1.x = acc[i][j][2] + bb.x;
            v1.y = acc[i][j][3] + bb.y;
            if (RELU) {
                v0.x = fmaxf(v0.x, 0.0f); v0.y = fmaxf(v0.y, 0.0f);
                v1.x = fmaxf(v1.x, 0.0f); v1.y = fmaxf(v1.y, 0.0f);
            }
            *(float2*)&C[r0 * N + col] = v0;
            *(float2*)&C[(r0 + 8) * N + col] = v1;
        }
    }
}

// ---------------- GRU gate fusion -------------------------------------------
__global__ __launch_bounds__(256) void gru_gates(
    const float* __restrict__ gi, const float* __restrict__ gh,
    const float* __restrict__ hstate,
    float* __restrict__ out0, float* __restrict__ out1)
{
    int idx = blockIdx.x * 256 + threadIdx.x;
    int row = idx >> 6;
    int c = (idx & 63) << 2;
    long gbase = (long)row * G3 + c;
    long hbase = (long)row * H + c;

    float4 ir = *(const float4*)&gi[gbase];
    float4 iz = *(const float4*)&gi[gbase + 256];
    float4 in_ = *(const float4*)&gi[gbase + 512];
    float4 hr = *(const float4*)&gh[gbase];
    float4 hz = *(const float4*)&gh[gbase + 256];
    float4 hn = *(const float4*)&gh[gbase + 512];
    float4 hv = *(const float4*)&hstate[hbase];

    float4 o;
    { float r = sigm(ir.x + hr.x), z = sigm(iz.x + hz.x);
      float n = tanh_fast(in_.x + r * hn.x); o.x = (1.0f - z) * n + z * hv.x; }
    { float r = sigm(ir.y + hr.y), z = sigm(iz.y + hz.y);
      float n = tanh_fast(in_.y + r * hn.y); o.y = (1.0f - z) * n + z * hv.y; }
    { float r = sigm(ir.z + hr.z), z = sigm(iz.z + hz.z);
      float n = tanh_fast(in_.z + r * hn.z); o.z = (1.0f - z) * n + z * hv.z; }
    { float r = sigm(ir.w + hr.w), z = sigm(iz.w + hz.w);
      float n = tanh_fast(in_.w + r * hn.w); o.w = (1.0f - z) * n + z * hv.w; }
    *(float4*)&out0[hbase] = o;
    if (out1) *(float4*)&out1[hbase] = o;
}

// ---------------- neighbor extraction ----------------------------------------
__global__ __launch_bounds__(256) void nb_kernel(
    const float* __restrict__ inp, float* __restrict__ nb, float* __restrict__ invn)
{
    int idx = blockIdx.x * 256 + threadIdx.x;
    int row = idx >> 5;
    int j = idx & 31;
    int i = row & 31;
    float v = 0.0f;
    if (j != i) {
        int k = (j > i) ? (j - 1) : j;
        v = inp[(long)row * IN_SHAPE + 260 + 8 * k];
    }
    float s = v;
#pragma unroll
    for (int o = 16; o > 0; o >>= 1) s += __shfl_xor_sync(0xffffffffu, s, o);
    nb[idx] = v;
    if (j == 0) invn[row] = 1.0f / s;
}

// ---------------- comm mix ---------------------------------------------------
__global__ __launch_bounds__(256) void comm_mix(
    const float* __restrict__ h, const float* __restrict__ nb,
    const float* __restrict__ invn, float* __restrict__ out)
{
    __shared__ float hs[32][256];
    __shared__ float At[32][36];
    __shared__ float sinv[32];

    int b = blockIdx.x;
    int tid = threadIdx.x;
    const float* hb = h + (long)b * 32 * 256;

#pragma unroll
    for (int t = tid; t < 2048; t += 256) {
        int r = t >> 6;
        int c4 = (t & 63) << 2;
        *(float4*)&hs[r][c4] = *(const float4*)&hb[r * 256 + c4];
    }
#pragma unroll
    for (int t = tid; t < 1024; t += 256) {
        int i = t >> 5;
        int j = t & 31;
        At[j][i] = nb[(long)(b * 32 + i) * 32 + j];
    }
    if (tid < 32) sinv[tid] = invn[b * 32 + tid];
    __syncthreads();

    float acc[32];
#pragma unroll
    for (int i = 0; i < 32; i++) acc[i] = 0.0f;

#pragma unroll 4
    for (int j = 0; j < 32; j++) {
        float hv = hs[j][tid];
#pragma unroll
        for (int i4 = 0; i4 < 32; i4 += 4) {
            float4 a = *(const float4*)&At[j][i4];
            acc[i4 + 0] += a.x * hv;
            acc[i4 + 1] += a.y * hv;
            acc[i4 + 2] += a.z * hv;
            acc[i4 + 3] += a.w * hv;
        }
    }
#pragma unroll
    for (int i = 0; i < 32; i++)
        out[(long)(b * 32 + i) * 256 + tid] = acc[i] * sinv[i];
}

// ---------------- q projection -----------------------------------------------
__global__ __launch_bounds__(256) void qproj(
    const float* __restrict__ h, const float* __restrict__ W2,
    const float* __restrict__ b2, float* __restrict__ q)
{
    __shared__ float ws[16][260];
    __shared__ float hsm[16][256];
    int tid = threadIdx.x;

#pragma unroll
    for (int t = tid; t < 1024; t += 256) {
        int n = t >> 6;
        int k4 = (t & 63) << 2;
        *(float4*)&ws[n][k4] = *(const float4*)&W2[n * 256 + k4];
    }
    const float* hb = h + (long)blockIdx.x * 16 * 256;
#pragma unroll
    for (int t = tid; t < 1024; t += 256) {
        int r = t >> 6;
        int k4 = (t & 63) << 2;
        *(float4*)&hsm[r][k4] = *(const float4*)&hb[r * 256 + k4];
    }
    __syncthreads();

    int r = tid >> 4;
    int n = tid & 15;
    float s = 0.0f;
#pragma unroll 8
    for (int k = 0; k < 256; k += 4) {
        float4 hv = *(const float4*)&hsm[r][k];
        float4 wv = *(const float4*)&ws[n][k];
        s += hv.x * wv.x + hv.y * wv.y + hv.z * wv.z + hv.w * wv.w;
    }
    q[(long)(blockIdx.x * 16 + r) * 16 + n] = s + b2[n];
}

// ---------------- orchestration ----------------------------------------------
extern "C" void kernel_launch(void* const* d_in, const int* in_sizes, int n_in,
                              void* d_out, int out_size)
{
    (void)in_sizes; (void)n_in; (void)out_size;
    const float* inputs = (const float*)d_in[0];
    const float* hidden = (const float*)d_in[1];
    const float* W1     = (const float*)d_in[2];
    const float* b1     = (const float*)d_in[3];
    const float* rWih   = (const float*)d_in[4];
    const float* rWhh   = (const float*)d_in[5];
    const float* rbih   = (const float*)d_in[6];
    const float* rbhh   = (const float*)d_in[7];
    const float* cWih   = (const float*)d_in[8];
    const float* cWhh   = (const float*)d_in[9];
    const float* cbih   = (const float*)d_in[10];
    const float* cbhh   = (const float*)d_in[11];
    const float* W2     = (const float*)d_in[12];
    const float* b2     = (const float*)d_in[13];

    float* q_out = (float*)d_out;
    float* hrnn_out = q_out + (long)ROWS * NACT;

    float *x, *gi, *gh, *h0, *h1, *c, *nb, *invn;
    cudaGetSymbolAddress((void**)&x, g_x);
    cudaGetSymbolAddress((void**)&gi, g_gi);
    cudaGetSymbolAddress((void**)&gh, g_gh);
    cudaGetSymbolAddress((void**)&h0, g_h0);
    cudaGetSymbolAddress((void**)&h1, g_h1);
    cudaGetSymbolAddress((void**)&c, g_c);
    cudaGetSymbolAddress((void**)&nb, g_nb);
    cudaGetSymbolAddress((void**)&invn, g_invn);

    dim3 blk(256);

    nb_kernel<<<ROWS * 32 / 256, blk>>>(inputs, nb, invn);

    // x = relu(inputs @ W1^T + b1)
    gemm_mma<1><<<dim3(H / 128, ROWS / 128), blk>>>(inputs, W1, b1, x, ROWS, H, IN_SHAPE);

    // h_rnn = GRU(x, hidden)
    gemm_mma<0><<<dim3(G3 / 128, ROWS / 128), blk>>>(x, rWih, rbih, gi, ROWS, G3, H);
    gemm_mma<0><<<dim3(G3 / 128, ROWS / 128), blk>>>(hidden, rWhh, rbhh, gh, ROWS, G3, H);
    gru_gates<<<ROWS * 64 / 256, blk>>>(gi, gh, hidden, h0, hrnn_out);

    float* hc = h0;
    float* hn = h1;
    for (int s = 0; s < 4; s++) {
        comm_mix<<<ROWS / NA, blk>>>(hc, nb, invn, c);
        gemm_mma<0><<<dim3(G3 / 128, ROWS / 128), blk>>>(hc, cWih, cbih, gi, ROWS, G3, H);
        gemm_mma<0><<<dim3(G3 / 128, ROWS / 128), blk>>>(c, cWhh, cbhh, gh, ROWS, G3, H);
        gru_gates<<<ROWS * 64 / 256, blk>>>(gi, gh, c, hn, nullptr);
        float* t2 = hc; hc = hn; hn = t2;
    }

    qproj<<<ROWS / 16, blk>>>(hc, W2, b2, q_out);
}

// round 9
// speedup vs baseline: 1.8992x; 1.4704x over previous
#include <cuda_runtime.h>
#include <cuda_fp16.h>
#include <cstdint>

#define ROWS 65536
#define H 256
#define IN_SHAPE 512
#define NA 32
#define NACT 16
#define G3 768   // 3*H

// ---------------- scratch (allocation-free: __device__ globals) -------------
__device__ float g_x [(size_t)ROWS * H];
__device__ float g_gi[(size_t)ROWS * G3];
__device__ float g_gh[(size_t)ROWS * G3];
__device__ float g_h0[(size_t)ROWS * H];
__device__ float g_h1[(size_t)ROWS * H];
__device__ float g_c [(size_t)ROWS * H];
__device__ float g_nb[(size_t)ROWS * NA];
__device__ float g_invn[(size_t)ROWS];

__device__ __forceinline__ float sigm(float x) { return 1.0f / (1.0f + __expf(-x)); }
__device__ __forceinline__ float tanh_fast(float x) {
    return 2.0f / (1.0f + __expf(-2.0f * x)) - 1.0f;
}
__device__ __forceinline__ uint32_t smem_u32(const void* p) {
    uint32_t a;
    asm("{ .reg .u64 t; cvta.to.shared.u64 t, %1; cvt.u32.u64 %0, t; }"
        : "=r"(a) : "l"(p));
    return a;
}
__device__ __forceinline__ uint32_t h2pack(float lo, float hi) {
    __half2 h = __floats2half2_rn(lo, hi);
    return *(uint32_t*)&h;
}
__device__ __forceinline__ void lds64(uint32_t& a, uint32_t& b, uint32_t addr) {
    asm volatile("ld.shared.v2.b32 {%0,%1}, [%2];"
                 : "=r"(a), "=r"(b) : "r"(addr));
}

#define MMA_F16_16x8x16(d, a0, a1, a2, a3, b0, b1) \
    asm volatile( \
        "mma.sync.aligned.m16n8k16.row.col.f32.f16.f16.f32 " \
        "{%0,%1,%2,%3}, {%4,%5,%6,%7}, {%8,%9}, {%0,%1,%2,%3};" \
        : "+f"((d)[0]), "+f"((d)[1]), "+f"((d)[2]), "+f"((d)[3]) \
        : "r"(a0), "r"(a1), "r"(a2), "r"(a3), "r"(b0), "r"(b1))

// Each smem row: 32 halfs = 16 half2-words, permuted within 8-word blocks:
//   s(w) = (w & 8) + 2*(w & 3) + ((w >> 2) & 1)
// so fragment pair (w = kk*8 + tg, w + 4) sits at adjacent words -> LDS.64.
// RSTRIDE=24 words: 24*gr + 2*tg distinct mod 32 within each 16-lane phase.
#define RSTRIDE 24

// ---------------- fp16 mma.sync GEMM -----------------------------------------
// C[m,n] = sum_k A[m,k]*B[n,k] + bias[n]   (A: MxK, B: NxK, row-major fp32)
// BM=128, BN=128, BK=32; 8 warps as 2(M) x 4(N); warp tile 64x32.
template <int RELU>
__global__ __launch_bounds__(256) void gemm_mma(
    const float* __restrict__ A, const float* __restrict__ B,
    const float* __restrict__ bias, float* __restrict__ C,
    int M, int N, int K)
{
    __shared__ uint32_t As[128 * RSTRIDE];
    __shared__ uint32_t Bs[128 * RSTRIDE];

    const int tid = threadIdx.x;
    const int wid = tid >> 5;
    const int lane = tid & 31;
    const int gr = lane >> 2;
    const int tg = lane & 3;

    const int bm = blockIdx.y * 128;
    const int bn = blockIdx.x * 128;
    const int wm = (wid & 1) * 64;
    const int wn = (wid >> 1) * 32;

    const int lr = tid >> 3;        // rows lr, lr+32, lr+64, lr+96
    const int lf = tid & 7;         // float4 index within 32-k chunk

    const float* Ap = A + (long)(bm + lr) * K + lf * 4;
    const float* Bp = B + (long)(bn + lr) * K + lf * 4;
    const long strideA = (long)32 * K;

    // store word offsets for this thread's float4 -> half2 words w=2lf, 2lf+1
    const int il = lf & 3;
    const int sFirst = ((lf & 4) << 1) + (il & 1) * 4 + (il >> 1);  // s(2lf)
    // second word s(2lf+1) = sFirst + 2

    const uint32_t aBase = smem_u32(As);
    const uint32_t bBase = smem_u32(Bs);

    float acc[4][4][4];
#pragma unroll
    for (int i = 0; i < 4; i++)
#pragma unroll
        for (int j = 0; j < 4; j++)
#pragma unroll
            for (int e = 0; e < 4; e++) acc[i][j][e] = 0.0f;

    float4 ar[4], br[4];
#pragma unroll
    for (int i = 0; i < 4; i++) {
        ar[i] = *(const float4*)(Ap + i * strideA);
        br[i] = *(const float4*)(Bp + i * strideA);
    }

    for (int k0 = 0; k0 < K; k0 += 32) {
        __syncthreads();
#pragma unroll
        for (int i = 0; i < 4; i++) {
            const int r = lr + i * 32;
            uint32_t* aw = (uint32_t*)As + r * RSTRIDE + sFirst;
            uint32_t* bw = (uint32_t*)Bs + r * RSTRIDE + sFirst;
            aw[0] = h2pack(ar[i].x, ar[i].y);
            aw[2] = h2pack(ar[i].z, ar[i].w);
            bw[0] = h2pack(br[i].x, br[i].y);
            bw[2] = h2pack(br[i].z, br[i].w);
        }
        __syncthreads();

        if (k0 + 32 < K) {
#pragma unroll
            for (int i = 0; i < 4; i++) {
                ar[i] = *(const float4*)(Ap + (k0 + 32) + i * strideA);
                br[i] = *(const float4*)(Bp + (k0 + 32) + i * strideA);
            }
        }

#pragma unroll
        for (int kk = 0; kk < 2; kk++) {               // two k16 steps
            const uint32_t kwb = (uint32_t)(kk * 8 + 2 * tg) * 4u;
            uint32_t af[4][4];
            uint32_t bf[4][2];
#pragma unroll
            for (int i = 0; i < 4; i++) {
                const int r0 = wm + 16 * i + gr;
                lds64(af[i][0], af[i][2], aBase + (uint32_t)(r0 * RSTRIDE) * 4u + kwb);
                lds64(af[i][1], af[i][3], aBase + (uint32_t)((r0 + 8) * RSTRIDE) * 4u + kwb);
            }
#pragma unroll
            for (int j = 0; j < 4; j++) {
                const int n0 = wn + 8 * j + gr;
                lds64(bf[j][0], bf[j][1], bBase + (uint32_t)(n0 * RSTRIDE) * 4u + kwb);
            }
#pragma unroll
            for (int i = 0; i < 4; i++)
#pragma unroll
                for (int j = 0; j < 4; j++)
                    MMA_F16_16x8x16(acc[i][j], af[i][0], af[i][1], af[i][2], af[i][3],
                                    bf[j][0], bf[j][1]);
        }
    }

#pragma unroll
    for (int j = 0; j < 4; j++) {
        const int col = bn + wn + 8 * j + 2 * tg;
        const float2 bb = *(const float2*)&bias[col];
#pragma unroll
        for (int i = 0; i < 4; i++) {
            const long r0 = (long)(bm + wm + 16 * i + gr);
            float2 v0, v1;
            v0.x = acc[i][j][0] + bb.x;
            v0.y = acc[i][j][1] + bb.y;
            v1.x = acc[i][j][2] + bb.x;
            v1.y = acc[i][j][3] + bb.y;
            if (RELU) {
                v0.x = fmaxf(v0.x, 0.0f); v0.y = fmaxf(v0.y, 0.0f);
                v1.x = fmaxf(v1.x, 0.0f); v1.y = fmaxf(v1.y, 0.0f);
            }
            *(float2*)&C[r0 * N + col] = v0;
            *(float2*)&C[(r0 + 8) * N + col] = v1;
        }
    }
}

// ---------------- GRU gate fusion -------------------------------------------
__global__ __launch_bounds__(256) void gru_gates(
    const float* __restrict__ gi, const float* __restrict__ gh,
    const float* __restrict__ hstate,
    float* __restrict__ out0, float* __restrict__ out1)
{
    int idx = blockIdx.x * 256 + threadIdx.x;
    int row = idx >> 6;
    int c = (idx & 63) << 2;
    long gbase = (long)row * G3 + c;
    long hbase = (long)row * H + c;

    float4 ir = *(const float4*)&gi[gbase];
    float4 iz = *(const float4*)&gi[gbase + 256];
    float4 in_ = *(const float4*)&gi[gbase + 512];
    float4 hr = *(const float4*)&gh[gbase];
    float4 hz = *(const float4*)&gh[gbase + 256];
    float4 hn = *(const float4*)&gh[gbase + 512];
    float4 hv = *(const float4*)&hstate[hbase];

    float4 o;
    { float r = sigm(ir.x + hr.x), z = sigm(iz.x + hz.x);
      float n = tanh_fast(in_.x + r * hn.x); o.x = (1.0f - z) * n + z * hv.x; }
    { float r = sigm(ir.y + hr.y), z = sigm(iz.y + hz.y);
      float n = tanh_fast(in_.y + r * hn.y); o.y = (1.0f - z) * n + z * hv.y; }
    { float r = sigm(ir.z + hr.z), z = sigm(iz.z + hz.z);
      float n = tanh_fast(in_.z + r * hn.z); o.z = (1.0f - z) * n + z * hv.z; }
    { float r = sigm(ir.w + hr.w), z = sigm(iz.w + hz.w);
      float n = tanh_fast(in_.w + r * hn.w); o.w = (1.0f - z) * n + z * hv.w; }
    *(float4*)&out0[hbase] = o;
    if (out1) *(float4*)&out1[hbase] = o;
}

// ---------------- neighbor extraction ----------------------------------------
__global__ __launch_bounds__(256) void nb_kernel(
    const float* __restrict__ inp, float* __restrict__ nb, float* __restrict__ invn)
{
    int idx = blockIdx.x * 256 + threadIdx.x;
    int row = idx >> 5;
    int j = idx & 31;
    int i = row & 31;
    float v = 0.0f;
    if (j != i) {
        int k = (j > i) ? (j - 1) : j;
        v = inp[(long)row * IN_SHAPE + 260 + 8 * k];
    }
    float s = v;
#pragma unroll
    for (int o = 16; o > 0; o >>= 1) s += __shfl_xor_sync(0xffffffffu, s, o);
    nb[idx] = v;
    if (j == 0) invn[row] = 1.0f / s;
}

// ---------------- comm mix ---------------------------------------------------
__global__ __launch_bounds__(256) void comm_mix(
    const float* __restrict__ h, const float* __restrict__ nb,
    const float* __restrict__ invn, float* __restrict__ out)
{
    __shared__ float hs[32][256];
    __shared__ float At[32][36];
    __shared__ float sinv[32];

    int b = blockIdx.x;
    int tid = threadIdx.x;
    const float* hb = h + (long)b * 32 * 256;

#pragma unroll
    for (int t = tid; t < 2048; t += 256) {
        int r = t >> 6;
        int c4 = (t & 63) << 2;
        *(float4*)&hs[r][c4] = *(const float4*)&hb[r * 256 + c4];
    }
#pragma unroll
    for (int t = tid; t < 1024; t += 256) {
        int i = t >> 5;
        int j = t & 31;
        At[j][i] = nb[(long)(b * 32 + i) * 32 + j];
    }
    if (tid < 32) sinv[tid] = invn[b * 32 + tid];
    __syncthreads();

    float acc[32];
#pragma unroll
    for (int i = 0; i < 32; i++) acc[i] = 0.0f;

#pragma unroll 4
    for (int j = 0; j < 32; j++) {
        float hv = hs[j][tid];
#pragma unroll
        for (int i4 = 0; i4 < 32; i4 += 4) {
            float4 a = *(const float4*)&At[j][i4];
            acc[i4 + 0] += a.x * hv;
            acc[i4 + 1] += a.y * hv;
            acc[i4 + 2] += a.z * hv;
            acc[i4 + 3] += a.w * hv;
        }
    }
#pragma unroll
    for (int i = 0; i < 32; i++)
        out[(long)(b * 32 + i) * 256 + tid] = acc[i] * sinv[i];
}

// ---------------- q projection -----------------------------------------------
__global__ __launch_bounds__(256) void qproj(
    const float* __restrict__ h, const float* __restrict__ W2,
    const float* __restrict__ b2, float* __restrict__ q)
{
    __shared__ float ws[16][260];
    __shared__ float hsm[16][256];
    int tid = threadIdx.x;

#pragma unroll
    for (int t = tid; t < 1024; t += 256) {
        int n = t >> 6;
        int k4 = (t & 63) << 2;
        *(float4*)&ws[n][k4] = *(const float4*)&W2[n * 256 + k4];
    }
    const float* hb = h + (long)blockIdx.x * 16 * 256;
#pragma unroll
    for (int t = tid; t < 1024; t += 256) {
        int r = t >> 6;
        int k4 = (t & 63) << 2;
        *(float4*)&hsm[r][k4] = *(const float4*)&hb[r * 256 + k4];
    }
    __syncthreads();

    int r = tid >> 4;
    int n = tid & 15;
    float s = 0.0f;
#pragma unroll 8
    for (int k = 0; k < 256; k += 4) {
        float4 hv = *(const float4*)&hsm[r][k];
        float4 wv = *(const float4*)&ws[n][k];
        s += hv.x * wv.x + hv.y * wv.y + hv.z * wv.z + hv.w * wv.w;
    }
    q[(long)(blockIdx.x * 16 + r) * 16 + n] = s + b2[n];
}

// ---------------- orchestration ----------------------------------------------
extern "C" void kernel_launch(void* const* d_in, const int* in_sizes, int n_in,
                              void* d_out, int out_size)
{
    (void)in_sizes; (void)n_in; (void)out_size;
    const float* inputs = (const float*)d_in[0];
    const float* hidden = (const float*)d_in[1];
    const float* W1     = (const float*)d_in[2];
    const float* b1     = (const float*)d_in[3];
    const float* rWih   = (const float*)d_in[4];
    const float* rWhh   = (const float*)d_in[5];
    const float* rbih   = (const float*)d_in[6];
    const float* rbhh   = (const float*)d_in[7];
    const float* cWih   = (const float*)d_in[8];
    const float* cWhh   = (const float*)d_in[9];
    const float* cbih   = (const float*)d_in[10];
    const float* cbhh   = (const float*)d_in[11];
    const float* W2     = (const float*)d_in[12];
    const float* b2     = (const float*)d_in[13];

    float* q_out = (float*)d_out;
    float* hrnn_out = q_out + (long)ROWS * NACT;

    float *x, *gi, *gh, *h0, *h1, *c, *nb, *invn;
    cudaGetSymbolAddress((void**)&x, g_x);
    cudaGetSymbolAddress((void**)&gi, g_gi);
    cudaGetSymbolAddress((void**)&gh, g_gh);
    cudaGetSymbolAddress((void**)&h0, g_h0);
    cudaGetSymbolAddress((void**)&h1, g_h1);
    cudaGetSymbolAddress((void**)&c, g_c);
    cudaGetSymbolAddress((void**)&nb, g_nb);
    cudaGetSymbolAddress((void**)&invn, g_invn);

    dim3 blk(256);

    nb_kernel<<<ROWS * 32 / 256, blk>>>(inputs, nb, invn);

    // x = relu(inputs @ W1^T + b1)
    gemm_mma<1><<<dim3(H / 128, ROWS / 128), blk>>>(inputs, W1, b1, x, ROWS, H, IN_SHAPE);

    // h_rnn = GRU(x, hidden)
    gemm_mma<0><<<dim3(G3 / 128, ROWS / 128), blk>>>(x, rWih, rbih, gi, ROWS, G3, H);
    gemm_mma<0><<<dim3(G3 / 128, ROWS / 128), blk>>>(hidden, rWhh, rbhh, gh, ROWS, G3, H);
    gru_gates<<<ROWS * 64 / 256, blk>>>(gi, gh, hidden, h0, hrnn_out);

    float* hc = h0;
    float* hn = h1;
    for (int s = 0; s < 4; s++) {
        comm_mix<<<ROWS / NA, blk>>>(hc, nb, invn, c);
        gemm_mma<0><<<dim3(G3 / 128, ROWS / 128), blk>>>(hc, cWih, cbih, gi, ROWS, G3, H);
        gemm_mma<0><<<dim3(G3 / 128, ROWS / 128), blk>>>(c, cWhh, cbhh, gh, ROWS, G3, H);
        gru_gates<<<ROWS * 64 / 256, blk>>>(gi, gh, c, hn, nullptr);
        float* t2 = hc; hc = hn; hn = t2;
    }

    qproj<<<ROWS / 16, blk>>>(hc, W2, b2, q_out);
}